// round 1
// baseline (speedup 1.0000x reference)
#include <cuda_runtime.h>

// ============================================================================
// EdgeAggregatorGATED: ResGatedGraphConv with edge features.
//   out_i = sum_{e:(j->i)} sigmoid(kx[i] + qx[j] + ea@Wkq_e + bkq) * (vx[j] + ea@Wv_e + bv)
//           + x_i @ Wskip + bias
// where kx = x@Wk[:D], qx = x@Wq[:D], vx = x@Wv[:D], Wkq_e = Wk[D:]+Wq[D:].
//
// Kernel 1 (node): computes kx/qx/vx into __device__ scratch and writes
//                  out = x@Wskip + bias (initializes d_out).
// Kernel 2 (edge): fused per-edge linears (f32x2 packed FMA), gather, gate,
//                  and vectorized scatter-add (red.global.add.v4.f32).
// ============================================================================

#define MAXN 51200
__device__ float g_kx[MAXN * 64];
__device__ float g_qx[MAXN * 64];
__device__ float g_vx[MAXN * 64];

typedef unsigned long long u64;

__device__ __forceinline__ u64 pack2(float x, float y) {
    u64 r;
    asm("mov.b64 %0, {%1,%2};" : "=l"(r) : "f"(x), "f"(y));
    return r;
}
__device__ __forceinline__ void unpack2(u64 v, float& x, float& y) {
    asm("mov.b64 {%0,%1}, %2;" : "=f"(x), "=f"(y) : "l"(v));
}
// d = a * b + d  (packed fp32x2, exact fp32 semantics; sm_100+)
__device__ __forceinline__ void fma2(u64& d, u64 a, u64 b) {
    asm("fma.rn.f32x2 %0, %1, %2, %0;" : "+l"(d) : "l"(a), "l"(b));
}

__device__ __forceinline__ float fast_sigmoid(float s) {
    return __fdividef(1.0f, 1.0f + __expf(-s));
}

// ----------------------------------------------------------------------------
// Node kernel: half-warp per node, lane owns 4 output columns, 2 matrices per
// blockIdx.y part (part 0: kx,qx ; part 1: vx, skip+bias -> out).
// ----------------------------------------------------------------------------
__global__ __launch_bounds__(256) void node_kernel(
    const float* __restrict__ x,
    const float* __restrict__ Wk, const float* __restrict__ Wq,
    const float* __restrict__ Wv, const float* __restrict__ Wskip,
    const float* __restrict__ bias,
    float* __restrict__ out, int N)
{
    __shared__ float WA[64][64];  // 16KB
    __shared__ float WB[64][64];  // 16KB
    const int tid = threadIdx.x;
    const int part = blockIdx.y;
    const float* srcA = (part == 0) ? Wk : Wv;      // top 64 rows of (96,64)
    const float* srcB = (part == 0) ? Wq : Wskip;   // Wq top rows / Wskip (64,64)
    for (int i = tid; i < 4096; i += 256) {
        (&WA[0][0])[i] = srcA[i];
        (&WB[0][0])[i] = srcB[i];
    }
    __syncthreads();

    const int hw = tid >> 4;   // half-warp id 0..15
    const int l  = tid & 15;   // lane within half-warp, owns cols 4l..4l+3
    const int base = blockIdx.x * 128;
    float* outA = (part == 0) ? g_kx : g_vx;

    for (int it = 0; it < 8; ++it) {
        int n = base + it * 16 + hw;
        bool valid = (n < N);
        int nc = valid ? n : 0;
        const float2* xr = (const float2*)(x + (size_t)nc * 64);
        float2 a0 = xr[l];        // features 2l, 2l+1
        float2 a1 = xr[16 + l];   // features 32+2l, 32+2l+1

        u64 accA0 = 0, accA1 = 0, accB0 = 0, accB1 = 0;  // 0ULL == {0.f,0.f}

        #pragma unroll
        for (int p = 0; p < 16; ++p) {
            float ax = __shfl_sync(0xffffffffu, a0.x, p, 16);
            float ay = __shfl_sync(0xffffffffu, a0.y, p, 16);
            u64 ax2 = pack2(ax, ax), ay2 = pack2(ay, ay);
            ulonglong2 wa0 = *(const ulonglong2*)&WA[2 * p][4 * l];
            ulonglong2 wa1 = *(const ulonglong2*)&WA[2 * p + 1][4 * l];
            ulonglong2 wb0 = *(const ulonglong2*)&WB[2 * p][4 * l];
            ulonglong2 wb1 = *(const ulonglong2*)&WB[2 * p + 1][4 * l];
            fma2(accA0, ax2, wa0.x); fma2(accA1, ax2, wa0.y);
            fma2(accA0, ay2, wa1.x); fma2(accA1, ay2, wa1.y);
            fma2(accB0, ax2, wb0.x); fma2(accB1, ax2, wb0.y);
            fma2(accB0, ay2, wb1.x); fma2(accB1, ay2, wb1.y);
        }
        #pragma unroll
        for (int p = 0; p < 16; ++p) {
            float ax = __shfl_sync(0xffffffffu, a1.x, p, 16);
            float ay = __shfl_sync(0xffffffffu, a1.y, p, 16);
            u64 ax2 = pack2(ax, ax), ay2 = pack2(ay, ay);
            ulonglong2 wa0 = *(const ulonglong2*)&WA[32 + 2 * p][4 * l];
            ulonglong2 wa1 = *(const ulonglong2*)&WA[33 + 2 * p][4 * l];
            ulonglong2 wb0 = *(const ulonglong2*)&WB[32 + 2 * p][4 * l];
            ulonglong2 wb1 = *(const ulonglong2*)&WB[33 + 2 * p][4 * l];
            fma2(accA0, ax2, wa0.x); fma2(accA1, ax2, wa0.y);
            fma2(accA0, ay2, wa1.x); fma2(accA1, ay2, wa1.y);
            fma2(accB0, ax2, wb0.x); fma2(accB1, ax2, wb0.y);
            fma2(accB0, ay2, wb1.x); fma2(accB1, ay2, wb1.y);
        }

        if (valid) {
            float4 rA, rB;
            unpack2(accA0, rA.x, rA.y); unpack2(accA1, rA.z, rA.w);
            unpack2(accB0, rB.x, rB.y); unpack2(accB1, rB.z, rB.w);
            *(float4*)(outA + (size_t)n * 64 + 4 * l) = rA;
            if (part == 0) {
                *(float4*)(g_qx + (size_t)n * 64 + 4 * l) = rB;
            } else {
                float4 b4 = *(const float4*)(bias + 4 * l);
                rB.x += b4.x; rB.y += b4.y; rB.z += b4.z; rB.w += b4.w;
                *(float4*)(out + (size_t)n * 64 + 4 * l) = rB;
            }
        }
    }
}

// ----------------------------------------------------------------------------
// Edge kernel: half-warp processes 16 contiguous edges (2 at a time for
// shared-weight reuse). Lane owns 4 output cols. Combined kq edge-linear.
// ----------------------------------------------------------------------------
__device__ __forceinline__ void edge_finish(
    int src, int dst, int l,
    u64 kq0, u64 kq1, u64 av0, u64 av1,
    float* __restrict__ out)
{
    const float4 kd = *(const float4*)(g_kx + (size_t)dst * 64 + 4 * l);
    const float4 qs = *(const float4*)(g_qx + (size_t)src * 64 + 4 * l);
    const float4 vs = *(const float4*)(g_vx + (size_t)src * 64 + 4 * l);
    float s0, s1, s2, s3, v0, v1, v2, v3;
    unpack2(kq0, s0, s1); unpack2(kq1, s2, s3);
    unpack2(av0, v0, v1); unpack2(av1, v2, v3);
    s0 += kd.x + qs.x; s1 += kd.y + qs.y; s2 += kd.z + qs.z; s3 += kd.w + qs.w;
    v0 += vs.x; v1 += vs.y; v2 += vs.z; v3 += vs.w;
    float m0 = fast_sigmoid(s0) * v0;
    float m1 = fast_sigmoid(s1) * v1;
    float m2 = fast_sigmoid(s2) * v2;
    float m3 = fast_sigmoid(s3) * v3;
    float* p = out + (size_t)dst * 64 + 4 * l;
    asm volatile("red.global.add.v4.f32 [%0], {%1,%2,%3,%4};"
                 :: "l"(p), "f"(m0), "f"(m1), "f"(m2), "f"(m3) : "memory");
}

__global__ __launch_bounds__(256) void edge_kernel(
    const float* __restrict__ ea,
    const int* __restrict__ srcArr, const int* __restrict__ dstArr,
    const float* __restrict__ Wk, const float* __restrict__ bk,
    const float* __restrict__ Wq, const float* __restrict__ bq,
    const float* __restrict__ Wv, const float* __restrict__ bv,
    float* __restrict__ out, int E)
{
    __shared__ float WKQ[32][64];  // Wk_edge + Wq_edge, 8KB
    __shared__ float WV[32][64];   // Wv_edge, 8KB
    __shared__ float BKQ[64], BV[64];
    const int tid = threadIdx.x;
    for (int i = tid; i < 2048; i += 256) {
        (&WKQ[0][0])[i] = Wk[4096 + i] + Wq[4096 + i];
        (&WV[0][0])[i]  = Wv[4096 + i];
    }
    if (tid < 64) { BKQ[tid] = bk[tid] + bq[tid]; BV[tid] = bv[tid]; }
    __syncthreads();

    const int hw = tid >> 4;
    const int l  = tid & 15;
    const long base = (long)blockIdx.x * 256 + (long)hw * 16;
    const ulonglong2 bkq2 = *(const ulonglong2*)&BKQ[4 * l];
    const ulonglong2 bv2  = *(const ulonglong2*)&BV[4 * l];

    for (int it = 0; it < 8; ++it) {
        long e0 = base + 2 * it;
        long e1 = e0 + 1;
        bool va = (e0 < E), vb = (e1 < E);
        long eca = va ? e0 : 0, ecb = vb ? e1 : 0;
        int sA = srcArr[eca], dA = dstArr[eca];
        int sB = srcArr[ecb], dB = dstArr[ecb];
        float2 aA = ((const float2*)(ea + eca * 32))[l];  // feats 2l,2l+1
        float2 aB = ((const float2*)(ea + ecb * 32))[l];

        u64 kqA0 = bkq2.x, kqA1 = bkq2.y, kqB0 = bkq2.x, kqB1 = bkq2.y;
        u64 avA0 = bv2.x,  avA1 = bv2.y,  avB0 = bv2.x,  avB1 = bv2.y;

        #pragma unroll
        for (int p = 0; p < 16; ++p) {
            float axA = __shfl_sync(0xffffffffu, aA.x, p, 16);
            float ayA = __shfl_sync(0xffffffffu, aA.y, p, 16);
            float axB = __shfl_sync(0xffffffffu, aB.x, p, 16);
            float ayB = __shfl_sync(0xffffffffu, aB.y, p, 16);
            u64 axA2 = pack2(axA, axA), ayA2 = pack2(ayA, ayA);
            u64 axB2 = pack2(axB, axB), ayB2 = pack2(ayB, ayB);
            ulonglong2 k0 = *(const ulonglong2*)&WKQ[2 * p][4 * l];
            ulonglong2 k1 = *(const ulonglong2*)&WKQ[2 * p + 1][4 * l];
            ulonglong2 w0 = *(const ulonglong2*)&WV[2 * p][4 * l];
            ulonglong2 w1 = *(const ulonglong2*)&WV[2 * p + 1][4 * l];
            fma2(kqA0, axA2, k0.x); fma2(kqA1, axA2, k0.y);
            fma2(kqA0, ayA2, k1.x); fma2(kqA1, ayA2, k1.y);
            fma2(kqB0, axB2, k0.x); fma2(kqB1, axB2, k0.y);
            fma2(kqB0, ayB2, k1.x); fma2(kqB1, ayB2, k1.y);
            fma2(avA0, axA2, w0.x); fma2(avA1, axA2, w0.y);
            fma2(avA0, ayA2, w1.x); fma2(avA1, ayA2, w1.y);
            fma2(avB0, axB2, w0.x); fma2(avB1, axB2, w0.y);
            fma2(avB0, ayB2, w1.x); fma2(avB1, ayB2, w1.y);
        }

        if (va) edge_finish(sA, dA, l, kqA0, kqA1, avA0, avA1, out);
        if (vb) edge_finish(sB, dB, l, kqB0, kqB1, avB0, avB1, out);
    }
}

// ----------------------------------------------------------------------------
// Launch. Inputs (metadata order): x, edge_index, edge_attr, Wk, bk, Wq, bq,
// Wv, bv, Wskip, bias. Output: [N, 64] float32.
// ----------------------------------------------------------------------------
extern "C" void kernel_launch(void* const* d_in, const int* in_sizes, int n_in,
                              void* d_out, int out_size)
{
    const float* x     = (const float*)d_in[0];
    const int*   ei    = (const int*)d_in[1];
    const float* ea    = (const float*)d_in[2];
    const float* Wk    = (const float*)d_in[3];
    const float* bk    = (const float*)d_in[4];
    const float* Wq    = (const float*)d_in[5];
    const float* bq    = (const float*)d_in[6];
    const float* Wv    = (const float*)d_in[7];
    const float* bv    = (const float*)d_in[8];
    const float* Wskip = (const float*)d_in[9];
    const float* bias  = (const float*)d_in[10];
    float* out = (float*)d_out;

    int N = in_sizes[0] / 64;   // x is [N, 64]
    int E = in_sizes[2] / 32;   // edge_attr is [E, 32]

    dim3 ngrid((N + 127) / 128, 2);
    node_kernel<<<ngrid, 256>>>(x, Wk, Wq, Wv, Wskip, bias, out, N);

    // edge_index is [2, E]: row 0 = src (j), row 1 = dst (i)
    edge_kernel<<<(E + 255) / 256, 256>>>(ea, ei, ei + E,
                                          Wk, bk, Wq, bq, Wv, bv, out, E);
}

// round 3
// speedup vs baseline: 1.4453x; 1.4453x over previous
#include <cuda_runtime.h>

// ============================================================================
// EdgeAggregatorGATED: ResGatedGraphConv with edge features.
//   out_i = sum_{e:(j->i)} sigmoid(kx[i] + qx[j] + ea@Wkq_e + bkq) * (vx[j] + ea@Wv_e + bv)
//           + x_i @ Wskip + bias
// Round 2 (resubmit; prior bench was an infra failure): 4x register blocking
// (edges/nodes) to amortize shared weight LDS (ncu: l1tex 91.4% bottleneck).
// ============================================================================

#define MAXN 51200
__device__ float g_kx[MAXN * 64];
__device__ float g_qx[MAXN * 64];
__device__ float g_vx[MAXN * 64];

typedef unsigned long long u64;

__device__ __forceinline__ u64 pack2(float x, float y) {
    u64 r;
    asm("mov.b64 %0, {%1,%2};" : "=l"(r) : "f"(x), "f"(y));
    return r;
}
__device__ __forceinline__ void unpack2(u64 v, float& x, float& y) {
    asm("mov.b64 {%0,%1}, %2;" : "=f"(x), "=f"(y) : "l"(v));
}
// d = a * b + d  (packed fp32x2, exact fp32 semantics; sm_100+)
__device__ __forceinline__ void fma2(u64& d, u64 a, u64 b) {
    asm("fma.rn.f32x2 %0, %1, %2, %0;" : "+l"(d) : "l"(a), "l"(b));
}

__device__ __forceinline__ float fast_sigmoid(float s) {
    return __fdividef(1.0f, 1.0f + __expf(-s));
}

// ----------------------------------------------------------------------------
// Node kernel: half-warp per 4-node group, lane owns 4 output columns.
// part 0: kx,qx ; part 1: vx, skip+bias -> out.  R=4 node blocking.
// ----------------------------------------------------------------------------
__global__ __launch_bounds__(256, 2) void node_kernel(
    const float* __restrict__ x,
    const float* __restrict__ Wk, const float* __restrict__ Wq,
    const float* __restrict__ Wv, const float* __restrict__ Wskip,
    const float* __restrict__ bias,
    float* __restrict__ out, int N)
{
    __shared__ float WA[64][64];  // 16KB
    __shared__ float WB[64][64];  // 16KB
    const int tid = threadIdx.x;
    const int part = blockIdx.y;
    const float* srcA = (part == 0) ? Wk : Wv;      // top 64 rows of (96,64)
    const float* srcB = (part == 0) ? Wq : Wskip;   // Wq top rows / Wskip
    for (int i = tid; i < 4096; i += 256) {
        (&WA[0][0])[i] = srcA[i];
        (&WB[0][0])[i] = srcB[i];
    }
    __syncthreads();

    const int hw = tid >> 4;   // half-warp id 0..15
    const int l  = tid & 15;   // lane within half-warp, owns cols 4l..4l+3
    const int base = blockIdx.x * 128;
    float* outA = (part == 0) ? g_kx : g_vx;

    for (int it = 0; it < 2; ++it) {
        int n[4]; bool valid[4];
        float2 a0[4], a1[4];
        #pragma unroll
        for (int j = 0; j < 4; ++j) {
            n[j] = base + it * 64 + j * 16 + hw;
            valid[j] = (n[j] < N);
            int nc = valid[j] ? n[j] : 0;
            const float2* xr = (const float2*)(x + (size_t)nc * 64);
            a0[j] = xr[l];
            a1[j] = xr[16 + l];
        }

        u64 accA0[4], accA1[4], accB0[4], accB1[4];
        #pragma unroll
        for (int j = 0; j < 4; ++j) { accA0[j]=0; accA1[j]=0; accB0[j]=0; accB1[j]=0; }

        #pragma unroll
        for (int p = 0; p < 16; ++p) {
            ulonglong2 wa0 = *(const ulonglong2*)&WA[2 * p][4 * l];
            ulonglong2 wa1 = *(const ulonglong2*)&WA[2 * p + 1][4 * l];
            ulonglong2 wb0 = *(const ulonglong2*)&WB[2 * p][4 * l];
            ulonglong2 wb1 = *(const ulonglong2*)&WB[2 * p + 1][4 * l];
            #pragma unroll
            for (int j = 0; j < 4; ++j) {
                float ax = __shfl_sync(0xffffffffu, a0[j].x, p, 16);
                float ay = __shfl_sync(0xffffffffu, a0[j].y, p, 16);
                u64 ax2 = pack2(ax, ax), ay2 = pack2(ay, ay);
                fma2(accA0[j], ax2, wa0.x); fma2(accA1[j], ax2, wa0.y);
                fma2(accA0[j], ay2, wa1.x); fma2(accA1[j], ay2, wa1.y);
                fma2(accB0[j], ax2, wb0.x); fma2(accB1[j], ax2, wb0.y);
                fma2(accB0[j], ay2, wb1.x); fma2(accB1[j], ay2, wb1.y);
            }
        }
        #pragma unroll
        for (int p = 0; p < 16; ++p) {
            ulonglong2 wa0 = *(const ulonglong2*)&WA[32 + 2 * p][4 * l];
            ulonglong2 wa1 = *(const ulonglong2*)&WA[33 + 2 * p][4 * l];
            ulonglong2 wb0 = *(const ulonglong2*)&WB[32 + 2 * p][4 * l];
            ulonglong2 wb1 = *(const ulonglong2*)&WB[33 + 2 * p][4 * l];
            #pragma unroll
            for (int j = 0; j < 4; ++j) {
                float ax = __shfl_sync(0xffffffffu, a1[j].x, p, 16);
                float ay = __shfl_sync(0xffffffffu, a1[j].y, p, 16);
                u64 ax2 = pack2(ax, ax), ay2 = pack2(ay, ay);
                fma2(accA0[j], ax2, wa0.x); fma2(accA1[j], ax2, wa0.y);
                fma2(accA0[j], ay2, wa1.x); fma2(accA1[j], ay2, wa1.y);
                fma2(accB0[j], ax2, wb0.x); fma2(accB1[j], ax2, wb0.y);
                fma2(accB0[j], ay2, wb1.x); fma2(accB1[j], ay2, wb1.y);
            }
        }

        #pragma unroll
        for (int j = 0; j < 4; ++j) {
            if (!valid[j]) continue;
            float4 rA, rB;
            unpack2(accA0[j], rA.x, rA.y); unpack2(accA1[j], rA.z, rA.w);
            unpack2(accB0[j], rB.x, rB.y); unpack2(accB1[j], rB.z, rB.w);
            *(float4*)(outA + (size_t)n[j] * 64 + 4 * l) = rA;
            if (part == 0) {
                *(float4*)(g_qx + (size_t)n[j] * 64 + 4 * l) = rB;
            } else {
                float4 b4 = *(const float4*)(bias + 4 * l);
                rB.x += b4.x; rB.y += b4.y; rB.z += b4.z; rB.w += b4.w;
                *(float4*)(out + (size_t)n[j] * 64 + 4 * l) = rB;
            }
        }
    }
}

// ----------------------------------------------------------------------------
// Edge kernel: half-warp processes 16 contiguous edges, 4 at a time (R=4)
// to amortize shared weight reads. Lane owns 4 output cols. Combined kq.
// ----------------------------------------------------------------------------
__device__ __forceinline__ void edge_finish(
    int src, int dst, int l,
    u64 kq0, u64 kq1, u64 av0, u64 av1,
    float* __restrict__ out)
{
    const float4 kd = *(const float4*)(g_kx + (size_t)dst * 64 + 4 * l);
    const float4 qs = *(const float4*)(g_qx + (size_t)src * 64 + 4 * l);
    const float4 vs = *(const float4*)(g_vx + (size_t)src * 64 + 4 * l);
    float s0, s1, s2, s3, v0, v1, v2, v3;
    unpack2(kq0, s0, s1); unpack2(kq1, s2, s3);
    unpack2(av0, v0, v1); unpack2(av1, v2, v3);
    s0 += kd.x + qs.x; s1 += kd.y + qs.y; s2 += kd.z + qs.z; s3 += kd.w + qs.w;
    v0 += vs.x; v1 += vs.y; v2 += vs.z; v3 += vs.w;
    float m0 = fast_sigmoid(s0) * v0;
    float m1 = fast_sigmoid(s1) * v1;
    float m2 = fast_sigmoid(s2) * v2;
    float m3 = fast_sigmoid(s3) * v3;
    float* p = out + (size_t)dst * 64 + 4 * l;
    asm volatile("red.global.add.v4.f32 [%0], {%1,%2,%3,%4};"
                 :: "l"(p), "f"(m0), "f"(m1), "f"(m2), "f"(m3) : "memory");
}

__global__ __launch_bounds__(256, 2) void edge_kernel(
    const float* __restrict__ ea,
    const int* __restrict__ srcArr, const int* __restrict__ dstArr,
    const float* __restrict__ Wk, const float* __restrict__ bk,
    const float* __restrict__ Wq, const float* __restrict__ bq,
    const float* __restrict__ Wv, const float* __restrict__ bv,
    float* __restrict__ out, int E)
{
    __shared__ float WKQ[32][64];  // Wk_edge + Wq_edge, 8KB
    __shared__ float WV[32][64];   // Wv_edge, 8KB
    __shared__ float BKQ[64], BV[64];
    const int tid = threadIdx.x;
    for (int i = tid; i < 2048; i += 256) {
        (&WKQ[0][0])[i] = Wk[4096 + i] + Wq[4096 + i];
        (&WV[0][0])[i]  = Wv[4096 + i];
    }
    if (tid < 64) { BKQ[tid] = bk[tid] + bq[tid]; BV[tid] = bv[tid]; }
    __syncthreads();

    const int hw = tid >> 4;
    const int l  = tid & 15;
    const long base = (long)blockIdx.x * 256 + (long)hw * 16;
    const ulonglong2 bkq2 = *(const ulonglong2*)&BKQ[4 * l];
    const ulonglong2 bv2  = *(const ulonglong2*)&BV[4 * l];

    for (int it = 0; it < 4; ++it) {
        long e[4]; bool va[4];
        int s[4], d[4];
        float2 a[4];
        #pragma unroll
        for (int j = 0; j < 4; ++j) {
            e[j] = base + 4 * it + j;
            va[j] = (e[j] < E);
            long ec = va[j] ? e[j] : 0;
            s[j] = srcArr[ec];
            d[j] = dstArr[ec];
            a[j] = ((const float2*)(ea + ec * 32))[l];
        }

        u64 kq0[4], kq1[4], av0[4], av1[4];
        #pragma unroll
        for (int j = 0; j < 4; ++j) {
            kq0[j] = bkq2.x; kq1[j] = bkq2.y;
            av0[j] = bv2.x;  av1[j] = bv2.y;
        }

        #pragma unroll
        for (int p = 0; p < 16; ++p) {
            ulonglong2 k0 = *(const ulonglong2*)&WKQ[2 * p][4 * l];
            ulonglong2 k1 = *(const ulonglong2*)&WKQ[2 * p + 1][4 * l];
            ulonglong2 w0 = *(const ulonglong2*)&WV[2 * p][4 * l];
            ulonglong2 w1 = *(const ulonglong2*)&WV[2 * p + 1][4 * l];
            #pragma unroll
            for (int j = 0; j < 4; ++j) {
                float ax = __shfl_sync(0xffffffffu, a[j].x, p, 16);
                float ay = __shfl_sync(0xffffffffu, a[j].y, p, 16);
                u64 ax2 = pack2(ax, ax), ay2 = pack2(ay, ay);
                fma2(kq0[j], ax2, k0.x); fma2(kq1[j], ax2, k0.y);
                fma2(kq0[j], ay2, k1.x); fma2(kq1[j], ay2, k1.y);
                fma2(av0[j], ax2, w0.x); fma2(av1[j], ax2, w0.y);
                fma2(av0[j], ay2, w1.x); fma2(av1[j], ay2, w1.y);
            }
        }

        #pragma unroll
        for (int j = 0; j < 4; ++j) {
            if (va[j]) edge_finish(s[j], d[j], l, kq0[j], kq1[j], av0[j], av1[j], out);
        }
    }
}

// ----------------------------------------------------------------------------
// Launch. Inputs: x, edge_index, edge_attr, Wk, bk, Wq, bq, Wv, bv, Wskip, bias.
// ----------------------------------------------------------------------------
extern "C" void kernel_launch(void* const* d_in, const int* in_sizes, int n_in,
                              void* d_out, int out_size)
{
    const float* x     = (const float*)d_in[0];
    const int*   ei    = (const int*)d_in[1];
    const float* ea    = (const float*)d_in[2];
    const float* Wk    = (const float*)d_in[3];
    const float* bk    = (const float*)d_in[4];
    const float* Wq    = (const float*)d_in[5];
    const float* bq    = (const float*)d_in[6];
    const float* Wv    = (const float*)d_in[7];
    const float* bv    = (const float*)d_in[8];
    const float* Wskip = (const float*)d_in[9];
    const float* bias  = (const float*)d_in[10];
    float* out = (float*)d_out;

    int N = in_sizes[0] / 64;   // x is [N, 64]
    int E = in_sizes[2] / 32;   // edge_attr is [E, 32]

    dim3 ngrid((N + 127) / 128, 2);
    node_kernel<<<ngrid, 256>>>(x, Wk, Wq, Wv, Wskip, bias, out, N);

    // edge_index is [2, E]: row 0 = src (j), row 1 = dst (i)
    edge_kernel<<<(E + 255) / 256, 256>>>(ea, ei, ei + E,
                                          Wk, bk, Wq, bq, Wv, bv, out, E);
}